// round 4
// baseline (speedup 1.0000x reference)
#include <cuda_runtime.h>
#include <cfloat>
#include <math.h>

#define FULL 0xffffffffu

constexpr int B = 4;
constexpr int N = 8192;
constexpr int M = 4096;
constexpr int F = 64;
constexpr int K = 16;
constexpr float MIN_SIGMA = 1e-4f;

constexpr int   NB   = 64;        // 1-D slabs along x
constexpr float XLO  = -3.2f;
constexpr float XW   = 0.1f;
constexpr float XINVW = 10.0f;
constexpr float EPS  = 1e-5f;     // conservative pad for fp-rounded bin edges

// Scratch (no allocations allowed)
__device__ float  g_featT[(size_t)B * N * F];   // (B,N,F) transposed features
__device__ float4 g_sorted[B * N];              // {x,y,z,bitcast(orig idx)}, bin-sorted
__device__ int    g_start[B * (NB + 1)];        // exclusive bin offsets

// ---------------------------------------------------------------------------
// Build: histogram + scan + scatter for one batch, single kernel.
// ---------------------------------------------------------------------------
__global__ void build_kernel(const float* __restrict__ pc) {
    __shared__ int cnt[NB];
    __shared__ int st[NB + 1];
    const int b = blockIdx.x;
    const int tid = threadIdx.x;
    const float* p = pc + (size_t)b * 3 * N;

    for (int i = tid; i < NB; i += blockDim.x) cnt[i] = 0;
    __syncthreads();
    for (int n = tid; n < N; n += blockDim.x) {
        const int s = min(NB - 1, max(0, (int)floorf((p[n] - XLO) * XINVW)));
        atomicAdd(&cnt[s], 1);
    }
    __syncthreads();
    if (tid == 0) {
        int acc = 0;
        for (int s = 0; s < NB; s++) { st[s] = acc; acc += cnt[s]; }
        st[NB] = acc;
    }
    __syncthreads();
    for (int i = tid; i < NB; i += blockDim.x) cnt[i] = st[i];      // cursors
    for (int i = tid; i < NB + 1; i += blockDim.x) g_start[b * (NB + 1) + i] = st[i];
    __syncthreads();
    for (int n = tid; n < N; n += blockDim.x) {
        const float x = p[n], y = p[N + n], z = p[2 * N + n];
        const int s = min(NB - 1, max(0, (int)floorf((x - XLO) * XINVW)));
        const int pos = atomicAdd(&cnt[s], 1);
        g_sorted[b * N + pos] = make_float4(x, y, z, __int_as_float(n));
    }
}

// ---------------------------------------------------------------------------
__global__ void transpose_feat_kernel(const float* __restrict__ feat) {
    __shared__ float tile[32][33];
    const int b  = blockIdx.z;
    const int n0 = blockIdx.x * 32;
    const int f0 = blockIdx.y * 32;
    const int tx = threadIdx.x, ty = threadIdx.y;
    #pragma unroll
    for (int i = ty; i < 32; i += 8)
        tile[i][tx] = feat[(size_t)b * F * N + (size_t)(f0 + i) * N + (n0 + tx)];
    __syncthreads();
    #pragma unroll
    for (int i = ty; i < 32; i += 8)
        g_featT[((size_t)b * N + (n0 + i)) * F + (f0 + tx)] = tile[tx][i];
}

// ---------------------------------------------------------------------------
// Query kernel: one warp per query. 1-D slab expansion with exact pruning;
// top-16 kept as sorted list in lanes 0..15, candidates collected into a
// 32-slot warp buffer, folded in by bitonic merges.
// ---------------------------------------------------------------------------
__global__ void __launch_bounds__(1024, 1)
soft_projection_query(const float* __restrict__ qc,
                      const float* __restrict__ temp,
                      float* __restrict__ out) {
    extern __shared__ char smraw[];
    float4* spts = (float4*)smraw;                                   // 128KB
    float*  swv  = (float*)(smraw + (size_t)N * sizeof(float4));     // 4KB staging vals
    int*    swi  = (int*)  (smraw + (size_t)N * sizeof(float4) + 32 * 32 * 4); // 4KB idx
    int*    cst  = (int*)  (smraw + (size_t)N * sizeof(float4) + 2 * 32 * 32 * 4);

    const int b = blockIdx.y;
    for (int i = threadIdx.x; i < N; i += blockDim.x) spts[i] = g_sorted[b * N + i];
    for (int i = threadIdx.x; i < NB + 1; i += blockDim.x)
        cst[i] = g_start[b * (NB + 1) + i];
    __syncthreads();

    const float t = *temp;
    const float inv_sigma = 1.0f / fmaxf(t * t, MIN_SIGMA);

    const int lane = threadIdx.x & 31;
    const int warp = threadIdx.x >> 5;
    float* mywv = swv + warp * 32;
    int*   mywi = swi + warp * 32;

    const int wg = blockIdx.x * 32 + warp;
    const int wstride = gridDim.x * 32;

    const float* qcb = qc + (size_t)b * 3 * M;
    float* out_pts  = out + (size_t)b * 3 * M;
    float* out_feat = out + (size_t)B * 3 * M + (size_t)b * F * M;
    const float* featb = g_featT + (size_t)b * N * F;

    for (int m = wg; m < M; m += wstride) {
        const float qx = qcb[m], qy = qcb[M + m], qz = qcb[2 * M + m];

        float val = FLT_MAX;   // sorted top-16 in lanes 0..15
        int   idx = 0;
        float th  = FLT_MAX;   // current 16th-best (warp-uniform)
        float bufv = FLT_MAX;  // 32-slot candidate buffer (lane = slot)
        int   bufi = 0;
        int   bcnt = 0;        // warp-uniform fill count

        // Merge buffer (sorted) into list: sort-32 + bitonic merge-48(keep 16).
        auto do_merge = [&]() {
            #pragma unroll
            for (int k = 2; k <= 32; k <<= 1) {
                #pragma unroll
                for (int j = k >> 1; j > 0; j >>= 1) {
                    const float ov = __shfl_xor_sync(FULL, bufv, j);
                    const int   oi = __shfl_xor_sync(FULL, bufi, j);
                    const bool ks = ((lane & j) == 0) == ((lane & k) == 0);
                    const bool swp = ks ? (ov < bufv) : (ov > bufv);
                    if (swp) { bufv = ov; bufi = oi; }
                }
            }
            const float a  = (lane < K) ? val : FLT_MAX;
            const int   ai = idx;
            const float brv = __shfl_sync(FULL, bufv, 31 - lane);
            const int   bri = __shfl_sync(FULL, bufi, 31 - lane);
            float mv; int mi;
            if (brv < a) { mv = brv; mi = bri; } else { mv = a; mi = ai; }
            #pragma unroll
            for (int j = 16; j > 0; j >>= 1) {
                const float ov = __shfl_xor_sync(FULL, mv, j);
                const int   oi = __shfl_xor_sync(FULL, mi, j);
                const bool ks = ((lane & j) == 0);
                const bool swp = ks ? (ov < mv) : (ov > mv);
                if (swp) { mv = ov; mi = oi; }
            }
            val = mv; idx = mi;
            th = __shfl_sync(FULL, mv, K - 1);
            bufv = FLT_MAX; bcnt = 0;
        };

        // Append all lanes with d2 < th into the buffer (compact via staging).
        auto collect = [&](float d2, int pid) {
            const unsigned bal = __ballot_sync(FULL, d2 < th);
            if (!bal) return;
            const int cnt = __popc(bal);
            if (bcnt + cnt > 32) do_merge();
            const int rank = __popc(bal & ((1u << lane) - 1));
            if ((bal >> lane) & 1u) { mywv[bcnt + rank] = d2; mywi[bcnt + rank] = pid; }
            __syncwarp();
            if (lane >= bcnt && lane < bcnt + cnt) { bufv = mywv[lane]; bufi = mywi[lane]; }
            bcnt += cnt;
            __syncwarp();
        };

        // Process one bin [s, e) in 128-point chunks (4 points/lane).
        auto chunk = [&](int s, int e) {
            for (int p0 = s; p0 < e; p0 += 128) {
                float d[4]; int pid[4];
                #pragma unroll
                for (int r = 0; r < 4; r++) {
                    const int pp = p0 + lane + r * 32;
                    pid[r] = pp;
                    d[r] = FLT_MAX;
                    if (pp < e) {
                        const float4 pt = spts[pp];
                        const float ax = pt.x - qx, ay = pt.y - qy, az = pt.z - qz;
                        d[r] = fmaf(ax, ax, fmaf(ay, ay, az * az));
                    }
                }
                const float mn = fminf(fminf(d[0], d[1]), fminf(d[2], d[3]));
                if (__any_sync(FULL, mn < th)) {
                    #pragma unroll
                    for (int r = 0; r < 4; r++) collect(d[r], pid[r]);
                }
            }
        };

        // Home bin, then two-pointer expansion by nearest bin-gap.
        const int h = min(NB - 1, max(0, (int)floorf((qx - XLO) * XINVW)));
        chunk(cst[h], cst[h + 1]);
        int l = h - 1, r = h + 1;
        while (true) {
            float dl2 = FLT_MAX, dr2 = FLT_MAX;
            if (l >= 0) {
                const float d = fmaxf(qx - (XLO + (l + 1) * XW) - EPS, 0.0f);
                dl2 = d * d;
            }
            if (r < NB) {
                const float d = fmaxf((XLO + r * XW) - qx - EPS, 0.0f);
                dr2 = d * d;
            }
            const bool goL = dl2 < dr2;
            const float dmin2 = goL ? dl2 : dr2;
            if (dmin2 >= th) break;
            if (goL) { chunk(cst[l], cst[l + 1]); l--; }
            else     { chunk(cst[r], cst[r + 1]); r++; }
        }
        if (bcnt > 0) do_merge();

        // --- softmax over sorted top-16 (lanes 0..15) ---
        const float s_min = __shfl_sync(FULL, val, 0);
        const float e = (lane < K) ? __expf(-(val - s_min) * inv_sigma) : 0.0f;
        float esum = e;
        #pragma unroll
        for (int o = 16; o; o >>= 1) esum += __shfl_xor_sync(FULL, esum, o);
        const float w = e / esum;

        // --- projected points ---
        const float4 gp = spts[idx];
        float wx = w * gp.x, wy = w * gp.y, wz = w * gp.z;
        #pragma unroll
        for (int o = 16; o; o >>= 1) {
            wx += __shfl_xor_sync(FULL, wx, o);
            wy += __shfl_xor_sync(FULL, wy, o);
            wz += __shfl_xor_sync(FULL, wz, o);
        }
        if (lane == 0) {
            out_pts[m]         = wx;
            out_pts[M + m]     = wy;
            out_pts[2 * M + m] = wz;
        }

        // --- propagated features: 2 channels per lane ---
        const int og = __float_as_int(gp.w);   // original point index
        float a0 = 0.f, a1 = 0.f;
        #pragma unroll
        for (int j = 0; j < K; j++) {
            const float wj = __shfl_sync(FULL, w, j);
            const int   gj = __shfl_sync(FULL, og, j);
            const float2 f2 = *reinterpret_cast<const float2*>(
                featb + (size_t)gj * F + lane * 2);
            a0 = fmaf(wj, f2.x, a0);
            a1 = fmaf(wj, f2.y, a1);
        }
        out_feat[(size_t)(2 * lane) * M + m]     = a0;
        out_feat[(size_t)(2 * lane + 1) * M + m] = a1;
    }
}

// ---------------------------------------------------------------------------
extern "C" void kernel_launch(void* const* d_in, const int* in_sizes, int n_in,
                              void* d_out, int out_size) {
    const float* pc   = (const float*)d_in[0];  // (B,3,N)
    const float* qc   = (const float*)d_in[1];  // (B,3,M)
    const float* pf   = (const float*)d_in[2];  // (B,F,N)
    const float* temp = (const float*)d_in[3];  // scalar
    float* out = (float*)d_out;                 // (B,3,M) ++ (B,F,M)
    (void)in_sizes; (void)n_in; (void)out_size;

    const int smem = N * (int)sizeof(float4)        // points
                   + 2 * 32 * 32 * 4                // staging
                   + (NB + 1) * (int)sizeof(int);   // bin offsets
    cudaFuncSetAttribute(soft_projection_query,
                         cudaFuncAttributeMaxDynamicSharedMemorySize, smem);

    build_kernel<<<B, 1024>>>(pc);
    transpose_feat_kernel<<<dim3(N / 32, F / 32, B), dim3(32, 8)>>>(pf);
    soft_projection_query<<<dim3(37, B), 1024, smem>>>(qc, temp, out);
}

// round 5
// speedup vs baseline: 1.1927x; 1.1927x over previous
#include <cuda_runtime.h>
#include <cfloat>
#include <math.h>

#define FULL 0xffffffffu

constexpr int B = 4;
constexpr int N = 8192;
constexpr int M = 4096;
constexpr int F = 64;
constexpr int K = 16;
constexpr float MIN_SIGMA = 1e-4f;

constexpr int   NB    = 128;      // x-bins
constexpr float XLO   = -3.2f;
constexpr float XW    = 0.05f;
constexpr float XINVW = 20.0f;

// Scratch (no allocations allowed)
__device__ float  g_featT[(size_t)B * N * F];   // (B,N,F) transposed features
__device__ float4 g_sorted[B * N];              // {x,y,z,bitcast(orig idx)}, x-bin-sorted
__device__ int    g_cnt[B * NB];                // histogram, then scatter cursors
__device__ int    g_start[B * (NB + 1)];        // exclusive bin offsets

// ---------------------------------------------------------------------------
__device__ __forceinline__ int xbin(float x) {
    return min(NB - 1, max(0, (int)floorf((x - XLO) * XINVW)));
}

__global__ void zero_kernel() {
    int i = blockIdx.x * blockDim.x + threadIdx.x;
    if (i < B * NB) g_cnt[i] = 0;
}

__global__ void hist_kernel(const float* __restrict__ pc) {
    int t = blockIdx.x * blockDim.x + threadIdx.x;
    if (t >= B * N) return;
    const int b = t >> 13, n = t & (N - 1);
    atomicAdd(&g_cnt[b * NB + xbin(pc[(size_t)b * 3 * N + n])], 1);
}

// One 32-thread warp per batch: scan 128 bins (4/lane).
__global__ void scan_kernel() {
    const int b = blockIdx.x, lane = threadIdx.x;
    const int base = b * NB + lane * 4;
    int v0 = g_cnt[base], v1 = g_cnt[base + 1], v2 = g_cnt[base + 2], v3 = g_cnt[base + 3];
    const int tsum = v0 + v1 + v2 + v3;
    int inc = tsum;
    #pragma unroll
    for (int off = 1; off < 32; off <<= 1) {
        int nb = __shfl_up_sync(FULL, inc, off);
        if (lane >= off) inc += nb;
    }
    int acc = inc - tsum;
    const int sb = b * (NB + 1) + lane * 4;
    g_start[sb]     = acc; g_cnt[base]     = acc; acc += v0;
    g_start[sb + 1] = acc; g_cnt[base + 1] = acc; acc += v1;
    g_start[sb + 2] = acc; g_cnt[base + 2] = acc; acc += v2;
    g_start[sb + 3] = acc; g_cnt[base + 3] = acc; acc += v3;
    if (lane == 31) g_start[b * (NB + 1) + NB] = acc;   // == N
}

__global__ void scatter_kernel(const float* __restrict__ pc) {
    int t = blockIdx.x * blockDim.x + threadIdx.x;
    if (t >= B * N) return;
    const int b = t >> 13, n = t & (N - 1);
    const float* p = pc + (size_t)b * 3 * N;
    const float x = p[n], y = p[N + n], z = p[2 * N + n];
    const int pos = atomicAdd(&g_cnt[b * NB + xbin(x)], 1);
    g_sorted[b * N + pos] = make_float4(x, y, z, __int_as_float(n));
}

// ---------------------------------------------------------------------------
__global__ void transpose_feat_kernel(const float* __restrict__ feat) {
    __shared__ float tile[32][33];
    const int b  = blockIdx.z;
    const int n0 = blockIdx.x * 32;
    const int f0 = blockIdx.y * 32;
    const int tx = threadIdx.x, ty = threadIdx.y;
    #pragma unroll
    for (int i = ty; i < 32; i += 8)
        tile[i][tx] = feat[(size_t)b * F * N + (size_t)(f0 + i) * N + (n0 + tx)];
    __syncthreads();
    #pragma unroll
    for (int i = ty; i < 32; i += 8)
        g_featT[((size_t)b * N + (n0 + i)) * F + (f0 + tx)] = tile[tx][i];
}

// ---------------------------------------------------------------------------
// Warp-cooperative top-K insert: sorted ascending list in lanes 0..K-1,
// candidates from any lane. threshold = current K-th value (warp-uniform).
// ---------------------------------------------------------------------------
__device__ __forceinline__ void topk_insert(float s, int pidx, int lane,
                                            float& val, int& idx,
                                            float& threshold) {
    unsigned bal = __ballot_sync(FULL, s < threshold);
    while (bal) {
        const int src = __ffs(bal) - 1;
        bal &= bal - 1;
        const float cs = __shfl_sync(FULL, s, src);
        if (cs < threshold) {
            const int ci = __shfl_sync(FULL, pidx, src);
            const unsigned less = __ballot_sync(FULL, (lane < K) && (val <= cs));
            const int pos = __popc(less);
            const float ot = __shfl_up_sync(FULL, val, 1);
            const int   oi = __shfl_up_sync(FULL, idx, 1);
            if (lane < K) {
                if (lane == pos)     { val = cs; idx = ci; }
                else if (lane > pos) { val = ot; idx = oi; }
            }
            threshold = __shfl_sync(FULL, val, K - 1);
        }
    }
}

// ---------------------------------------------------------------------------
// Query kernel: one warp per query.
// Phase 1 (seed): fully process the 128 array-adjacent points around the
//   query's home bin -> sorted top-16 + threshold th (upper bound on d16).
// Phase 2: the exact candidate window {|px-qx| <= sqrt(th)} is ONE contiguous
//   index range (points x-sorted); scan it minus the seed range with the
//   tight vote-guarded loop.
// ---------------------------------------------------------------------------
__global__ void __launch_bounds__(1024, 1)
soft_projection_query(const float* __restrict__ qc,
                      const float* __restrict__ temp,
                      float* __restrict__ out) {
    extern __shared__ char smraw[];
    float4* spts = (float4*)smraw;                               // 128KB
    int* cst = (int*)(smraw + (size_t)N * sizeof(float4));       // (NB+1) ints

    const int b = blockIdx.y;
    for (int i = threadIdx.x; i < N; i += blockDim.x) spts[i] = g_sorted[b * N + i];
    for (int i = threadIdx.x; i < NB + 1; i += blockDim.x)
        cst[i] = g_start[b * (NB + 1) + i];
    __syncthreads();

    const float t = *temp;
    const float inv_sigma = 1.0f / fmaxf(t * t, MIN_SIGMA);

    const int lane = threadIdx.x & 31;
    const int warp = threadIdx.x >> 5;
    const int wg = blockIdx.x * 32 + warp;
    const int wstride = gridDim.x * 32;

    const float* qcb = qc + (size_t)b * 3 * M;
    float* out_pts  = out + (size_t)b * 3 * M;
    float* out_feat = out + (size_t)B * 3 * M + (size_t)b * F * M;
    const float* featb = g_featT + (size_t)b * N * F;

    for (int m = wg; m < M; m += wstride) {
        const float qx = qcb[m], qy = qcb[M + m], qz = qcb[2 * M + m];

        float val, th;
        int   idx;

        // ---- Phase 1: seed from 128 array-adjacent points ----
        const int h = xbin(qx);
        const int c = (cst[h] + cst[h + 1]) >> 1;
        const int s0 = min(max(c - 64, 0), N - 128);   // N >= 128 always

        {
            float d[4]; int pid[4];
            #pragma unroll
            for (int r = 0; r < 4; r++) {
                const int pp = s0 + lane + r * 32;
                const float4 pt = spts[pp];
                const float ax = pt.x - qx, ay = pt.y - qy, az = pt.z - qz;
                d[r] = fmaf(ax, ax, fmaf(ay, ay, az * az));
                pid[r] = pp;
            }
            // bitonic sort-32 ascending on (d[0], pid[0]) -> initial list
            float sv = d[0]; int si = pid[0];
            #pragma unroll
            for (int k = 2; k <= 32; k <<= 1) {
                #pragma unroll
                for (int j = k >> 1; j > 0; j >>= 1) {
                    const float ov = __shfl_xor_sync(FULL, sv, j);
                    const int   oi = __shfl_xor_sync(FULL, si, j);
                    const bool ks = ((lane & j) == 0) == ((lane & k) == 0);
                    const bool swp = ks ? (ov < sv) : (ov > sv);
                    if (swp) { sv = ov; si = oi; }
                }
            }
            val = sv; idx = si;
            th = __shfl_sync(FULL, val, K - 1);
            topk_insert(d[1], pid[1], lane, val, idx, th);
            topk_insert(d[2], pid[2], lane, val, idx, th);
            topk_insert(d[3], pid[3], lane, val, idx, th);
        }

        // ---- Phase 2: contiguous window scan (minus seed range) ----
        const float rr = sqrtf(th) + 1e-4f;
        const int blo = min(NB - 1, max(0, (int)floorf((qx - rr - XLO) * XINVW)));
        const int bhi = min(NB - 1, max(0, (int)floorf((qx + rr - XLO) * XINVW)));
        const int wlo = cst[blo];
        const int whi = cst[bhi + 1];

        auto scan_range = [&](int s, int e) {
            for (int p0 = s; p0 < e; p0 += 128) {
                float d[4]; int pid[4];
                #pragma unroll
                for (int r = 0; r < 4; r++) {
                    const int pp = p0 + lane + r * 32;
                    pid[r] = pp;
                    d[r] = FLT_MAX;
                    if (pp < e) {
                        const float4 pt = spts[pp];
                        const float ax = pt.x - qx, ay = pt.y - qy, az = pt.z - qz;
                        d[r] = fmaf(ax, ax, fmaf(ay, ay, az * az));
                    }
                }
                const float mn = fminf(fminf(d[0], d[1]), fminf(d[2], d[3]));
                if (__any_sync(FULL, mn < th)) {
                    topk_insert(d[0], pid[0], lane, val, idx, th);
                    topk_insert(d[1], pid[1], lane, val, idx, th);
                    topk_insert(d[2], pid[2], lane, val, idx, th);
                    topk_insert(d[3], pid[3], lane, val, idx, th);
                }
            }
        };

        scan_range(wlo, min(whi, s0));          // left of seed
        scan_range(max(wlo, s0 + 128), whi);    // right of seed

        // ---- softmax over sorted top-16 (lanes 0..15) ----
        const float s_min = __shfl_sync(FULL, val, 0);
        const float e = (lane < K) ? __expf(-(val - s_min) * inv_sigma) : 0.0f;
        float esum = e;
        #pragma unroll
        for (int o = 16; o; o >>= 1) esum += __shfl_xor_sync(FULL, esum, o);
        const float w = e / esum;

        // ---- projected points ----
        const float4 gp = spts[idx];
        float wx = w * gp.x, wy = w * gp.y, wz = w * gp.z;
        #pragma unroll
        for (int o = 16; o; o >>= 1) {
            wx += __shfl_xor_sync(FULL, wx, o);
            wy += __shfl_xor_sync(FULL, wy, o);
            wz += __shfl_xor_sync(FULL, wz, o);
        }
        if (lane == 0) {
            out_pts[m]         = wx;
            out_pts[M + m]     = wy;
            out_pts[2 * M + m] = wz;
        }

        // ---- propagated features: 2 channels per lane ----
        const int og = __float_as_int(gp.w);   // original point index
        float a0 = 0.f, a1 = 0.f;
        #pragma unroll
        for (int j = 0; j < K; j++) {
            const float wj = __shfl_sync(FULL, w, j);
            const int   gj = __shfl_sync(FULL, og, j);
            const float2 f2 = *reinterpret_cast<const float2*>(
                featb + (size_t)gj * F + lane * 2);
            a0 = fmaf(wj, f2.x, a0);
            a1 = fmaf(wj, f2.y, a1);
        }
        out_feat[(size_t)(2 * lane) * M + m]     = a0;
        out_feat[(size_t)(2 * lane + 1) * M + m] = a1;
    }
}

// ---------------------------------------------------------------------------
extern "C" void kernel_launch(void* const* d_in, const int* in_sizes, int n_in,
                              void* d_out, int out_size) {
    const float* pc   = (const float*)d_in[0];  // (B,3,N)
    const float* qc   = (const float*)d_in[1];  // (B,3,M)
    const float* pf   = (const float*)d_in[2];  // (B,F,N)
    const float* temp = (const float*)d_in[3];  // scalar
    float* out = (float*)d_out;                 // (B,3,M) ++ (B,F,M)
    (void)in_sizes; (void)n_in; (void)out_size;

    const int smem = N * (int)sizeof(float4) + (NB + 1) * (int)sizeof(int);
    cudaFuncSetAttribute(soft_projection_query,
                         cudaFuncAttributeMaxDynamicSharedMemorySize, smem);

    zero_kernel<<<1, B * NB>>>();
    hist_kernel<<<32, 1024>>>(pc);
    scan_kernel<<<B, 32>>>();
    scatter_kernel<<<32, 1024>>>(pc);
    transpose_feat_kernel<<<dim3(N / 32, F / 32, B), dim3(32, 8)>>>(pf);
    soft_projection_query<<<dim3(37, B), 1024, smem>>>(qc, temp, out);
}

// round 6
// speedup vs baseline: 1.4207x; 1.1911x over previous
#include <cuda_runtime.h>
#include <cfloat>
#include <math.h>

#define FULL 0xffffffffu

constexpr int B = 4;
constexpr int N = 8192;
constexpr int M = 4096;
constexpr int F = 64;
constexpr int K = 16;
constexpr float MIN_SIGMA = 1e-4f;

constexpr int   NB    = 128;      // x-bins
constexpr float XLO   = -3.2f;
constexpr float XW    = 0.05f;
constexpr float XINVW = 20.0f;
constexpr float EPSP  = 1e-4f;    // conservative pad on bin-edge gaps

// Scratch (no allocations allowed)
__device__ float  g_featT[(size_t)B * N * F];   // (B,N,F) transposed features
__device__ float4 g_sorted[B * N];              // points {x,y,z,bits(n)}, x-bin-sorted
__device__ float4 g_qsorted[B * M];             // queries {x,y,z,bits(m)}, x-bin-sorted
__device__ int    g_cnt[2 * B * NB];            // histograms/cursors: [pts | queries]
__device__ int    g_start[B * (NB + 1)];        // point bin offsets

// ---------------------------------------------------------------------------
__device__ __forceinline__ int xbin(float x) {
    return min(NB - 1, max(0, (int)floorf((x - XLO) * XINVW)));
}

__global__ void zero_kernel() {
    int i = blockIdx.x * blockDim.x + threadIdx.x;
    if (i < 2 * B * NB) g_cnt[i] = 0;
}

// Combined histogram: points then queries.
__global__ void hist_kernel(const float* __restrict__ pc,
                            const float* __restrict__ qc) {
    int t = blockIdx.x * blockDim.x + threadIdx.x;
    if (t < B * N) {
        const int b = t >> 13, n = t & (N - 1);
        atomicAdd(&g_cnt[b * NB + xbin(pc[(size_t)b * 3 * N + n])], 1);
    } else if (t < B * N + B * M) {
        const int u = t - B * N;
        const int b = u >> 12, m = u & (M - 1);
        atomicAdd(&g_cnt[(B + b) * NB + xbin(qc[(size_t)b * 3 * M + m])], 1);
    }
}

// One warp per (kind,batch): exclusive scan of 128 bins (4/lane).
__global__ void scan_kernel() {
    const int g = blockIdx.x;          // 0..2B-1 ; g<B: points, else queries
    const int lane = threadIdx.x;
    const int base = g * NB + lane * 4;
    int v0 = g_cnt[base], v1 = g_cnt[base + 1], v2 = g_cnt[base + 2], v3 = g_cnt[base + 3];
    const int tsum = v0 + v1 + v2 + v3;
    int inc = tsum;
    #pragma unroll
    for (int off = 1; off < 32; off <<= 1) {
        int nb = __shfl_up_sync(FULL, inc, off);
        if (lane >= off) inc += nb;
    }
    int acc = inc - tsum;
    g_cnt[base] = acc;
    if (g < B) g_start[g * (NB + 1) + lane * 4] = acc;
    acc += v0;
    g_cnt[base + 1] = acc;
    if (g < B) g_start[g * (NB + 1) + lane * 4 + 1] = acc;
    acc += v1;
    g_cnt[base + 2] = acc;
    if (g < B) g_start[g * (NB + 1) + lane * 4 + 2] = acc;
    acc += v2;
    g_cnt[base + 3] = acc;
    if (g < B) g_start[g * (NB + 1) + lane * 4 + 3] = acc;
    acc += v3;
    if (g < B && lane == 31) g_start[g * (NB + 1) + NB] = acc;
}

__global__ void scatter_kernel(const float* __restrict__ pc,
                               const float* __restrict__ qc) {
    int t = blockIdx.x * blockDim.x + threadIdx.x;
    if (t < B * N) {
        const int b = t >> 13, n = t & (N - 1);
        const float* p = pc + (size_t)b * 3 * N;
        const float x = p[n], y = p[N + n], z = p[2 * N + n];
        const int pos = atomicAdd(&g_cnt[b * NB + xbin(x)], 1);
        g_sorted[b * N + pos] = make_float4(x, y, z, __int_as_float(n));
    } else if (t < B * N + B * M) {
        const int u = t - B * N;
        const int b = u >> 12, m = u & (M - 1);
        const float* q = qc + (size_t)b * 3 * M;
        const float x = q[m], y = q[M + m], z = q[2 * M + m];
        const int pos = atomicAdd(&g_cnt[(B + b) * NB + xbin(x)], 1);
        g_qsorted[b * M + pos] = make_float4(x, y, z, __int_as_float(m));
    }
}

// ---------------------------------------------------------------------------
__global__ void transpose_feat_kernel(const float* __restrict__ feat) {
    __shared__ float tile[32][33];
    const int b  = blockIdx.z;
    const int n0 = blockIdx.x * 32;
    const int f0 = blockIdx.y * 32;
    const int tx = threadIdx.x, ty = threadIdx.y;
    #pragma unroll
    for (int i = ty; i < 32; i += 8)
        tile[i][tx] = feat[(size_t)b * F * N + (size_t)(f0 + i) * N + (n0 + tx)];
    __syncthreads();
    #pragma unroll
    for (int i = ty; i < 32; i += 8)
        g_featT[((size_t)b * N + (n0 + i)) * F + (f0 + tx)] = tile[tx][i];
}

// ---------------------------------------------------------------------------
// Warp-cooperative top-K insert into sorted 16-entry list held in lanes
// [base, base+16); candidates from any lane; threshold warp-uniform.
// ---------------------------------------------------------------------------
__device__ __forceinline__ void topk_insert(float s, int pidx, int lane,
                                            float& val, int& idx,
                                            float& threshold, int base) {
    unsigned bal = __ballot_sync(FULL, s < threshold);
    while (bal) {
        const int src = __ffs(bal) - 1;
        bal &= bal - 1;
        const float cs = __shfl_sync(FULL, s, src);
        if (cs < threshold) {
            const int ci = __shfl_sync(FULL, pidx, src);
            const bool mine = (unsigned)(lane - base) < (unsigned)K;
            const unsigned less = __ballot_sync(FULL, mine && (val <= cs));
            const int pos = base + __popc(less);
            const float ot = __shfl_up_sync(FULL, val, 1);
            const int   oi = __shfl_up_sync(FULL, idx, 1);
            if (mine) {
                if (lane == pos)     { val = cs; idx = ci; }
                else if (lane > pos) { val = ot; idx = oi; }
            }
            threshold = __shfl_sync(FULL, val, base + K - 1);
        }
    }
}

// ---------------------------------------------------------------------------
// Query kernel: one warp handles TWO x-adjacent (sorted) queries.
// Seed: bitonic-sort 32 array-adjacent points per query (independent chains).
// Scan: bin-wise outward expansion with dynamic (current-th) boundary test.
// Lists: query A in lanes 0..15, query B in lanes 16..31.
// ---------------------------------------------------------------------------
__global__ void __launch_bounds__(1024, 1)
soft_projection_query(const float* __restrict__ temp,
                      float* __restrict__ out) {
    extern __shared__ char smraw[];
    float4* spts = (float4*)smraw;                               // 128KB
    int* cst = (int*)(smraw + (size_t)N * sizeof(float4));       // NB+1 ints

    const int b = blockIdx.y;
    for (int i = threadIdx.x; i < N; i += blockDim.x) spts[i] = g_sorted[b * N + i];
    for (int i = threadIdx.x; i < NB + 1; i += blockDim.x)
        cst[i] = g_start[b * (NB + 1) + i];
    __syncthreads();

    const float t = *temp;
    const float inv_sigma = 1.0f / fmaxf(t * t, MIN_SIGMA);

    const int lane = threadIdx.x & 31;
    const int warp = threadIdx.x >> 5;
    const int wg = blockIdx.x * 32 + warp;
    const int wstride = gridDim.x * 32;

    float* out_pts  = out + (size_t)b * 3 * M;
    float* out_feat = out + (size_t)B * 3 * M + (size_t)b * F * M;
    const float* featb = g_featT + (size_t)b * N * F;
    const float4* qs = g_qsorted + (size_t)b * M;

    for (int task = wg; task < M / 2; task += wstride) {
        const float4 QA = qs[2 * task];
        const float4 QB = qs[2 * task + 1];
        const int mA = __float_as_int(QA.w);
        const int mB = __float_as_int(QB.w);

        float val, thA, thB;
        int   idx;

        // ---- seed: 32 points at the home bin start, bitonic per query ----
        const int h = xbin(0.5f * (QA.x + QB.x));
        const int s0 = min(cst[h], N - 32);
        {
            const float4 pt = spts[s0 + lane];
            const float aX = pt.x - QA.x, aY = pt.y - QA.y, aZ = pt.z - QA.z;
            const float bX = pt.x - QB.x, bY = pt.y - QB.y, bZ = pt.z - QB.z;
            float dA = fmaf(aX, aX, fmaf(aY, aY, aZ * aZ));
            float dB = fmaf(bX, bX, fmaf(bY, bY, bZ * bZ));
            int pA = s0 + lane, pB = s0 + lane;
            #pragma unroll
            for (int k = 2; k <= 32; k <<= 1) {
                #pragma unroll
                for (int j = k >> 1; j > 0; j >>= 1) {
                    const float ovA = __shfl_xor_sync(FULL, dA, j);
                    const int   oiA = __shfl_xor_sync(FULL, pA, j);
                    const float ovB = __shfl_xor_sync(FULL, dB, j);
                    const int   oiB = __shfl_xor_sync(FULL, pB, j);
                    const bool ks = ((lane & j) == 0) == ((lane & k) == 0);
                    if (ks ? (ovA < dA) : (ovA > dA)) { dA = ovA; pA = oiA; }
                    if (ks ? (ovB < dB) : (ovB > dB)) { dB = ovB; pB = oiB; }
                }
            }
            const float dBs = __shfl_sync(FULL, dB, lane - 16);
            const int   pBs = __shfl_sync(FULL, pB, lane - 16);
            val = (lane < 16) ? dA : dBs;
            idx = (lane < 16) ? pA : pBs;
            thA = __shfl_sync(FULL, val, K - 1);
            thB = __shfl_sync(FULL, val, 16 + K - 1);
        }

        // ---- scan one range [s,e) in 64-pt chunks, both queries ----
        auto scan_raw = [&](int s, int e) {
            for (int p0 = s; p0 < e; p0 += 64) {
                const int q0 = p0 + lane, q1 = p0 + lane + 32;
                float dA0 = FLT_MAX, dA1 = FLT_MAX, dB0 = FLT_MAX, dB1 = FLT_MAX;
                if (q0 < e) {
                    const float4 pt = spts[q0];
                    const float aX = pt.x - QA.x, aY = pt.y - QA.y, aZ = pt.z - QA.z;
                    const float bX = pt.x - QB.x, bY = pt.y - QB.y, bZ = pt.z - QB.z;
                    dA0 = fmaf(aX, aX, fmaf(aY, aY, aZ * aZ));
                    dB0 = fmaf(bX, bX, fmaf(bY, bY, bZ * bZ));
                }
                if (q1 < e) {
                    const float4 pt = spts[q1];
                    const float aX = pt.x - QA.x, aY = pt.y - QA.y, aZ = pt.z - QA.z;
                    const float bX = pt.x - QB.x, bY = pt.y - QB.y, bZ = pt.z - QB.z;
                    dA1 = fmaf(aX, aX, fmaf(aY, aY, aZ * aZ));
                    dB1 = fmaf(bX, bX, fmaf(bY, bY, bZ * bZ));
                }
                const bool c = (fminf(dA0, dA1) < thA) | (fminf(dB0, dB1) < thB);
                if (__any_sync(FULL, c)) {
                    topk_insert(dA0, q0, lane, val, idx, thA, 0);
                    topk_insert(dA1, q1, lane, val, idx, thA, 0);
                    topk_insert(dB0, q0, lane, val, idx, thB, 16);
                    topk_insert(dB1, q1, lane, val, idx, thB, 16);
                }
            }
        };
        // range minus the seed block [s0, s0+32)
        auto scan_range = [&](int s, int e) {
            scan_raw(s, min(e, s0));
            scan_raw(max(s, s0 + 32), e);
        };

        scan_range(cst[h], cst[h + 1]);   // home bin
        // left expansion with dynamic boundary
        for (int l = h - 1; l >= 0; l--) {
            const float edge = XLO + (l + 1) * XW;
            const float gA = QA.x - edge - EPSP;
            const float gB = QB.x - edge - EPSP;
            const bool stopA = (gA > 0.0f) && (gA * gA >= thA);
            const bool stopB = (gB > 0.0f) && (gB * gB >= thB);
            if (stopA && stopB) break;
            scan_range(cst[l], cst[l + 1]);
        }
        // right expansion
        for (int r = h + 1; r < NB; r++) {
            const float edge = XLO + r * XW;
            const float gA = edge - QA.x - EPSP;
            const float gB = edge - QB.x - EPSP;
            const bool stopA = (gA > 0.0f) && (gA * gA >= thA);
            const bool stopB = (gB > 0.0f) && (gB * gB >= thB);
            if (stopA && stopB) break;
            scan_range(cst[r], cst[r + 1]);
        }

        // ---- softmax per half-warp ----
        const int base = lane & 16;
        const float s_min = __shfl_sync(FULL, val, base);
        const float e = __expf(-(val - s_min) * inv_sigma);
        float esum = e;
        #pragma unroll
        for (int o = 8; o; o >>= 1) esum += __shfl_xor_sync(FULL, esum, o);
        const float w = e / esum;

        // ---- projected points ----
        const float4 gp = spts[idx];
        float wx = w * gp.x, wy = w * gp.y, wz = w * gp.z;
        #pragma unroll
        for (int o = 8; o; o >>= 1) {
            wx += __shfl_xor_sync(FULL, wx, o);
            wy += __shfl_xor_sync(FULL, wy, o);
            wz += __shfl_xor_sync(FULL, wz, o);
        }
        if (lane == 0) {
            out_pts[mA]         = wx;
            out_pts[M + mA]     = wy;
            out_pts[2 * M + mA] = wz;
        } else if (lane == 16) {
            out_pts[mB]         = wx;
            out_pts[M + mB]     = wy;
            out_pts[2 * M + mB] = wz;
        }

        // ---- propagated features: 2 channels/lane, both queries ----
        const int og = __float_as_int(gp.w);
        float a0 = 0.f, a1 = 0.f, c0 = 0.f, c1 = 0.f;
        #pragma unroll
        for (int j = 0; j < K; j++) {
            const float wj = __shfl_sync(FULL, w, j);
            const int   gj = __shfl_sync(FULL, og, j);
            const float2 f2 = *reinterpret_cast<const float2*>(
                featb + (size_t)gj * F + lane * 2);
            a0 = fmaf(wj, f2.x, a0);
            a1 = fmaf(wj, f2.y, a1);
        }
        #pragma unroll
        for (int j = 16; j < 16 + K; j++) {
            const float wj = __shfl_sync(FULL, w, j);
            const int   gj = __shfl_sync(FULL, og, j);
            const float2 f2 = *reinterpret_cast<const float2*>(
                featb + (size_t)gj * F + lane * 2);
            c0 = fmaf(wj, f2.x, c0);
            c1 = fmaf(wj, f2.y, c1);
        }
        out_feat[(size_t)(2 * lane) * M + mA]     = a0;
        out_feat[(size_t)(2 * lane + 1) * M + mA] = a1;
        out_feat[(size_t)(2 * lane) * M + mB]     = c0;
        out_feat[(size_t)(2 * lane + 1) * M + mB] = c1;
    }
}

// ---------------------------------------------------------------------------
extern "C" void kernel_launch(void* const* d_in, const int* in_sizes, int n_in,
                              void* d_out, int out_size) {
    const float* pc   = (const float*)d_in[0];  // (B,3,N)
    const float* qc   = (const float*)d_in[1];  // (B,3,M)
    const float* pf   = (const float*)d_in[2];  // (B,F,N)
    const float* temp = (const float*)d_in[3];  // scalar
    float* out = (float*)d_out;                 // (B,3,M) ++ (B,F,M)
    (void)in_sizes; (void)n_in; (void)out_size;

    const int smem = N * (int)sizeof(float4) + (NB + 1) * (int)sizeof(int);
    cudaFuncSetAttribute(soft_projection_query,
                         cudaFuncAttributeMaxDynamicSharedMemorySize, smem);

    const int tot = B * N + B * M;
    zero_kernel<<<1, 2 * B * NB>>>();
    hist_kernel<<<(tot + 1023) / 1024, 1024>>>(pc, qc);
    scan_kernel<<<2 * B, 32>>>();
    scatter_kernel<<<(tot + 1023) / 1024, 1024>>>(pc, qc);
    transpose_feat_kernel<<<dim3(N / 32, F / 32, B), dim3(32, 8)>>>(pf);
    soft_projection_query<<<dim3(37, B), 1024, smem>>>(temp, out);
}

// round 7
// speedup vs baseline: 1.7574x; 1.2370x over previous
#include <cuda_runtime.h>
#include <cfloat>
#include <math.h>

#define FULL 0xffffffffu

constexpr int B = 4;
constexpr int N = 8192;
constexpr int M = 4096;
constexpr int F = 64;
constexpr int K = 16;
constexpr float MIN_SIGMA = 1e-4f;

constexpr int   NB    = 128;      // x-bins
constexpr float XLO   = -3.2f;
constexpr float XW    = 0.05f;
constexpr float XINVW = 20.0f;
constexpr float EPSP  = 1e-4f;    // conservative pad on bin-edge gaps

// Scratch (no allocations allowed)
__device__ float  g_featT[(size_t)B * N * F];   // (B,N,F) transposed features
__device__ float4 g_sorted[B * N];              // points {x,y,z,bits(n)}, x-bin-sorted
__device__ float4 g_qsorted[B * M];             // queries {x,y,z,bits(m)}, x-bin-sorted
__device__ int    g_cnt[2 * B * NB];            // histograms/cursors: [pts | queries]
__device__ int    g_start[B * (NB + 1)];        // point bin offsets
__device__ int    g_task[B];                    // dynamic task counters

// ---------------------------------------------------------------------------
__device__ __forceinline__ int xbin(float x) {
    return min(NB - 1, max(0, (int)floorf((x - XLO) * XINVW)));
}

__global__ void zero_kernel() {
    int i = blockIdx.x * blockDim.x + threadIdx.x;
    if (i < 2 * B * NB) g_cnt[i] = 0;
    if (i < B) g_task[i] = 0;
}

// Combined histogram: points then queries.
__global__ void hist_kernel(const float* __restrict__ pc,
                            const float* __restrict__ qc) {
    int t = blockIdx.x * blockDim.x + threadIdx.x;
    if (t < B * N) {
        const int b = t >> 13, n = t & (N - 1);
        atomicAdd(&g_cnt[b * NB + xbin(pc[(size_t)b * 3 * N + n])], 1);
    } else if (t < B * N + B * M) {
        const int u = t - B * N;
        const int b = u >> 12, m = u & (M - 1);
        atomicAdd(&g_cnt[(B + b) * NB + xbin(qc[(size_t)b * 3 * M + m])], 1);
    }
}

// One warp per (kind,batch): exclusive scan of 128 bins (4/lane).
__global__ void scan_kernel() {
    const int g = blockIdx.x;          // 0..2B-1 ; g<B: points, else queries
    const int lane = threadIdx.x;
    const int base = g * NB + lane * 4;
    int v0 = g_cnt[base], v1 = g_cnt[base + 1], v2 = g_cnt[base + 2], v3 = g_cnt[base + 3];
    const int tsum = v0 + v1 + v2 + v3;
    int inc = tsum;
    #pragma unroll
    for (int off = 1; off < 32; off <<= 1) {
        int nb = __shfl_up_sync(FULL, inc, off);
        if (lane >= off) inc += nb;
    }
    int acc = inc - tsum;
    g_cnt[base] = acc;
    if (g < B) g_start[g * (NB + 1) + lane * 4] = acc;
    acc += v0;
    g_cnt[base + 1] = acc;
    if (g < B) g_start[g * (NB + 1) + lane * 4 + 1] = acc;
    acc += v1;
    g_cnt[base + 2] = acc;
    if (g < B) g_start[g * (NB + 1) + lane * 4 + 2] = acc;
    acc += v2;
    g_cnt[base + 3] = acc;
    if (g < B) g_start[g * (NB + 1) + lane * 4 + 3] = acc;
    acc += v3;
    if (g < B && lane == 31) g_start[g * (NB + 1) + NB] = acc;
}

__global__ void scatter_kernel(const float* __restrict__ pc,
                               const float* __restrict__ qc) {
    int t = blockIdx.x * blockDim.x + threadIdx.x;
    if (t < B * N) {
        const int b = t >> 13, n = t & (N - 1);
        const float* p = pc + (size_t)b * 3 * N;
        const float x = p[n], y = p[N + n], z = p[2 * N + n];
        const int pos = atomicAdd(&g_cnt[b * NB + xbin(x)], 1);
        g_sorted[b * N + pos] = make_float4(x, y, z, __int_as_float(n));
    } else if (t < B * N + B * M) {
        const int u = t - B * N;
        const int b = u >> 12, m = u & (M - 1);
        const float* q = qc + (size_t)b * 3 * M;
        const float x = q[m], y = q[M + m], z = q[2 * M + m];
        const int pos = atomicAdd(&g_cnt[(B + b) * NB + xbin(x)], 1);
        g_qsorted[b * M + pos] = make_float4(x, y, z, __int_as_float(m));
    }
}

// ---------------------------------------------------------------------------
__global__ void transpose_feat_kernel(const float* __restrict__ feat) {
    __shared__ float tile[32][33];
    const int b  = blockIdx.z;
    const int n0 = blockIdx.x * 32;
    const int f0 = blockIdx.y * 32;
    const int tx = threadIdx.x, ty = threadIdx.y;
    #pragma unroll
    for (int i = ty; i < 32; i += 8)
        tile[i][tx] = feat[(size_t)b * F * N + (size_t)(f0 + i) * N + (n0 + tx)];
    __syncthreads();
    #pragma unroll
    for (int i = ty; i < 32; i += 8)
        g_featT[((size_t)b * N + (n0 + i)) * F + (f0 + tx)] = tile[tx][i];
}

// ---------------------------------------------------------------------------
// Warp-cooperative top-K insert into sorted 16-entry list held in lanes
// [base, base+16); candidates from any lane; threshold warp-uniform.
// ---------------------------------------------------------------------------
__device__ __forceinline__ void topk_insert(float s, int pidx, int lane,
                                            float& val, int& idx,
                                            float& threshold, int base) {
    unsigned bal = __ballot_sync(FULL, s < threshold);
    while (bal) {
        const int src = __ffs(bal) - 1;
        bal &= bal - 1;
        const float cs = __shfl_sync(FULL, s, src);
        if (cs < threshold) {
            const int ci = __shfl_sync(FULL, pidx, src);
            const bool mine = (unsigned)(lane - base) < (unsigned)K;
            const unsigned less = __ballot_sync(FULL, mine && (val <= cs));
            const int pos = base + __popc(less);
            const float ot = __shfl_up_sync(FULL, val, 1);
            const int   oi = __shfl_up_sync(FULL, idx, 1);
            if (mine) {
                if (lane == pos)     { val = cs; idx = ci; }
                else if (lane > pos) { val = ot; idx = oi; }
            }
            threshold = __shfl_sync(FULL, val, base + K - 1);
        }
    }
}

// ---------------------------------------------------------------------------
// Query kernel: one warp handles TWO x-adjacent (sorted) queries per task,
// tasks grabbed dynamically (center-out order: longest tasks first).
// ---------------------------------------------------------------------------
__global__ void __launch_bounds__(1024, 1)
soft_projection_query(const float* __restrict__ temp,
                      float* __restrict__ out) {
    extern __shared__ char smraw[];
    float4* spts = (float4*)smraw;                               // 128KB
    int* cst = (int*)(smraw + (size_t)N * sizeof(float4));       // NB+1 ints

    const int b = blockIdx.y;
    for (int i = threadIdx.x; i < N; i += blockDim.x) spts[i] = g_sorted[b * N + i];
    for (int i = threadIdx.x; i < NB + 1; i += blockDim.x)
        cst[i] = g_start[b * (NB + 1) + i];
    __syncthreads();

    const float t = *temp;
    const float inv_sigma = 1.0f / fmaxf(t * t, MIN_SIGMA);

    const int lane = threadIdx.x & 31;

    float* out_pts  = out + (size_t)b * 3 * M;
    float* out_feat = out + (size_t)B * 3 * M + (size_t)b * F * M;
    const float* featb = g_featT + (size_t)b * N * F;
    const float4* qs = g_qsorted + (size_t)b * M;

    constexpr int NT = M / 2;         // 2048 tasks per batch
    while (true) {
        int pos;
        if (lane == 0) pos = atomicAdd(&g_task[b], 1);
        pos = __shfl_sync(FULL, pos, 0);
        if (pos >= NT) break;
        // center-out order: 1024, 1023, 1025, 1022, ... (longest-first)
        const int task = (NT / 2) + ((pos & 1) ? -((pos + 1) >> 1) : (pos >> 1));

        const float4 QA = qs[2 * task];
        const float4 QB = qs[2 * task + 1];
        const int mA = __float_as_int(QA.w);
        const int mB = __float_as_int(QB.w);

        float val, thA, thB;
        int   idx;

        // ---- seed: 32 points at the home bin start, bitonic per query ----
        const int h = xbin(0.5f * (QA.x + QB.x));
        const int s0 = min(cst[h], N - 32);
        {
            const float4 pt = spts[s0 + lane];
            const float aX = pt.x - QA.x, aY = pt.y - QA.y, aZ = pt.z - QA.z;
            const float bX = pt.x - QB.x, bY = pt.y - QB.y, bZ = pt.z - QB.z;
            float dA = fmaf(aX, aX, fmaf(aY, aY, aZ * aZ));
            float dB = fmaf(bX, bX, fmaf(bY, bY, bZ * bZ));
            int pA = s0 + lane, pB = s0 + lane;
            #pragma unroll
            for (int k = 2; k <= 32; k <<= 1) {
                #pragma unroll
                for (int j = k >> 1; j > 0; j >>= 1) {
                    const float ovA = __shfl_xor_sync(FULL, dA, j);
                    const int   oiA = __shfl_xor_sync(FULL, pA, j);
                    const float ovB = __shfl_xor_sync(FULL, dB, j);
                    const int   oiB = __shfl_xor_sync(FULL, pB, j);
                    const bool ks = ((lane & j) == 0) == ((lane & k) == 0);
                    if (ks ? (ovA < dA) : (ovA > dA)) { dA = ovA; pA = oiA; }
                    if (ks ? (ovB < dB) : (ovB > dB)) { dB = ovB; pB = oiB; }
                }
            }
            const float dBs = __shfl_sync(FULL, dB, lane - 16);
            const int   pBs = __shfl_sync(FULL, pB, lane - 16);
            val = (lane < 16) ? dA : dBs;
            idx = (lane < 16) ? pA : pBs;
            thA = __shfl_sync(FULL, val, K - 1);
            thB = __shfl_sync(FULL, val, 16 + K - 1);
        }

        // ---- scan one range [s,e) in 64-pt chunks, both queries ----
        auto scan_raw = [&](int s, int e) {
            for (int p0 = s; p0 < e; p0 += 64) {
                const int q0 = p0 + lane, q1 = p0 + lane + 32;
                float dA0 = FLT_MAX, dA1 = FLT_MAX, dB0 = FLT_MAX, dB1 = FLT_MAX;
                if (q0 < e) {
                    const float4 pt = spts[q0];
                    const float aX = pt.x - QA.x, aY = pt.y - QA.y, aZ = pt.z - QA.z;
                    const float bX = pt.x - QB.x, bY = pt.y - QB.y, bZ = pt.z - QB.z;
                    dA0 = fmaf(aX, aX, fmaf(aY, aY, aZ * aZ));
                    dB0 = fmaf(bX, bX, fmaf(bY, bY, bZ * bZ));
                }
                if (q1 < e) {
                    const float4 pt = spts[q1];
                    const float aX = pt.x - QA.x, aY = pt.y - QA.y, aZ = pt.z - QA.z;
                    const float bX = pt.x - QB.x, bY = pt.y - QB.y, bZ = pt.z - QB.z;
                    dA1 = fmaf(aX, aX, fmaf(aY, aY, aZ * aZ));
                    dB1 = fmaf(bX, bX, fmaf(bY, bY, bZ * bZ));
                }
                const bool c = (fminf(dA0, dA1) < thA) | (fminf(dB0, dB1) < thB);
                if (__any_sync(FULL, c)) {
                    topk_insert(dA0, q0, lane, val, idx, thA, 0);
                    topk_insert(dA1, q1, lane, val, idx, thA, 0);
                    topk_insert(dB0, q0, lane, val, idx, thB, 16);
                    topk_insert(dB1, q1, lane, val, idx, thB, 16);
                }
            }
        };
        // range minus the seed block [s0, s0+32)
        auto scan_range = [&](int s, int e) {
            scan_raw(s, min(e, s0));
            scan_raw(max(s, s0 + 32), e);
        };

        scan_range(cst[h], cst[h + 1]);   // home bin
        // left expansion with dynamic boundary
        for (int l = h - 1; l >= 0; l--) {
            const float edge = XLO + (l + 1) * XW;
            const float gA = QA.x - edge - EPSP;
            const float gB = QB.x - edge - EPSP;
            const bool stopA = (gA > 0.0f) && (gA * gA >= thA);
            const bool stopB = (gB > 0.0f) && (gB * gB >= thB);
            if (stopA && stopB) break;
            scan_range(cst[l], cst[l + 1]);
        }
        // right expansion
        for (int r = h + 1; r < NB; r++) {
            const float edge = XLO + r * XW;
            const float gA = edge - QA.x - EPSP;
            const float gB = edge - QB.x - EPSP;
            const bool stopA = (gA > 0.0f) && (gA * gA >= thA);
            const bool stopB = (gB > 0.0f) && (gB * gB >= thB);
            if (stopA && stopB) break;
            scan_range(cst[r], cst[r + 1]);
        }

        // ---- softmax per half-warp ----
        const int base = lane & 16;
        const float s_min = __shfl_sync(FULL, val, base);
        const float e = __expf(-(val - s_min) * inv_sigma);
        float esum = e;
        #pragma unroll
        for (int o = 8; o; o >>= 1) esum += __shfl_xor_sync(FULL, esum, o);
        const float w = e / esum;

        // ---- projected points ----
        const float4 gp = spts[idx];
        float wx = w * gp.x, wy = w * gp.y, wz = w * gp.z;
        #pragma unroll
        for (int o = 8; o; o >>= 1) {
            wx += __shfl_xor_sync(FULL, wx, o);
            wy += __shfl_xor_sync(FULL, wy, o);
            wz += __shfl_xor_sync(FULL, wz, o);
        }
        if (lane == 0) {
            out_pts[mA]         = wx;
            out_pts[M + mA]     = wy;
            out_pts[2 * M + mA] = wz;
        } else if (lane == 16) {
            out_pts[mB]         = wx;
            out_pts[M + mB]     = wy;
            out_pts[2 * M + mB] = wz;
        }

        // ---- propagated features: 2 channels/lane, both queries ----
        const int og = __float_as_int(gp.w);
        float a0 = 0.f, a1 = 0.f, c0 = 0.f, c1 = 0.f;
        #pragma unroll
        for (int j = 0; j < K; j++) {
            const float wj = __shfl_sync(FULL, w, j);
            const int   gj = __shfl_sync(FULL, og, j);
            const float2 f2 = *reinterpret_cast<const float2*>(
                featb + (size_t)gj * F + lane * 2);
            a0 = fmaf(wj, f2.x, a0);
            a1 = fmaf(wj, f2.y, a1);
        }
        #pragma unroll
        for (int j = 16; j < 16 + K; j++) {
            const float wj = __shfl_sync(FULL, w, j);
            const int   gj = __shfl_sync(FULL, og, j);
            const float2 f2 = *reinterpret_cast<const float2*>(
                featb + (size_t)gj * F + lane * 2);
            c0 = fmaf(wj, f2.x, c0);
            c1 = fmaf(wj, f2.y, c1);
        }
        out_feat[(size_t)(2 * lane) * M + mA]     = a0;
        out_feat[(size_t)(2 * lane + 1) * M + mA] = a1;
        out_feat[(size_t)(2 * lane) * M + mB]     = c0;
        out_feat[(size_t)(2 * lane + 1) * M + mB] = c1;
    }
}

// ---------------------------------------------------------------------------
extern "C" void kernel_launch(void* const* d_in, const int* in_sizes, int n_in,
                              void* d_out, int out_size) {
    const float* pc   = (const float*)d_in[0];  // (B,3,N)
    const float* qc   = (const float*)d_in[1];  // (B,3,M)
    const float* pf   = (const float*)d_in[2];  // (B,F,N)
    const float* temp = (const float*)d_in[3];  // scalar
    float* out = (float*)d_out;                 // (B,3,M) ++ (B,F,M)
    (void)in_sizes; (void)n_in; (void)out_size;

    const int smem = N * (int)sizeof(float4) + (NB + 1) * (int)sizeof(int);
    cudaFuncSetAttribute(soft_projection_query,
                         cudaFuncAttributeMaxDynamicSharedMemorySize, smem);

    const int tot = B * N + B * M;
    zero_kernel<<<1, 1024>>>();
    hist_kernel<<<(tot + 1023) / 1024, 1024>>>(pc, qc);
    scan_kernel<<<2 * B, 32>>>();
    scatter_kernel<<<(tot + 1023) / 1024, 1024>>>(pc, qc);
    transpose_feat_kernel<<<dim3(N / 32, F / 32, B), dim3(32, 8)>>>(pf);
    soft_projection_query<<<dim3(37, B), 1024, smem>>>(temp, out);
}